// round 8
// baseline (speedup 1.0000x reference)
#include <cuda_runtime.h>

// SoftmaxProbs: mean = (1/B) * sum_{b,c} l[b,c] * (lse_b - x[b,c])
// 2M rows x 18 classes fp32, HBM-bound (288 MB).
// x: cp.async double-buffered smem staging (row access for lse).
// l: streamed elementwise from gmem (never touches smem).

#define NC 18
#define BLK 128
#define CHUNK_FLOATS (BLK * NC)      // 2304 floats = 9216 B per stage
#define MAX_GRID 2048

__device__ double       g_partials[MAX_GRID];
__device__ unsigned int g_count = 0;

__device__ __forceinline__ void cpa16(unsigned int saddr, const float4* g) {
    asm volatile("cp.async.cg.shared.global [%0], [%1], 16;" :: "r"(saddr), "l"(g));
}
__device__ __forceinline__ void cpa_commit() {
    asm volatile("cp.async.commit_group;");
}

__global__ __launch_bounds__(BLK, 10)
void ce_main_kernel(const float* __restrict__ x,
                    const float* __restrict__ lab,
                    float* __restrict__ out,
                    int B, int nchunks)
{
    __shared__ float  sx[2][CHUNK_FLOATS];   // 18432 B
    __shared__ float  rowlse[BLK];           // 512 B
    __shared__ double sred[BLK / 32];
    __shared__ int    s_last;

    const int tid = threadIdx.x;

    auto stage_x = [&](int c, int s) {
        const long long row0 = (long long)c * BLK;
        long long rem = (long long)B - row0;
        const int rows = rem < BLK ? (int)rem : BLK;
        const int nf   = rows * NC;
        const int nv4  = nf >> 2;
        const float*  xb  = x + row0 * NC;
        const float4* xb4 = (const float4*)xb;
        const unsigned int sxa = (unsigned int)__cvta_generic_to_shared(&sx[s][0]);
        for (int i = tid; i < nv4; i += BLK)
            cpa16(sxa + i * 16, xb4 + i);
        for (int i = (nv4 << 2) + tid; i < nf; i += BLK)   // tail (last chunk only)
            sx[s][i] = xb[i];
    };

    const int c0 = blockIdx.x;
    double acc = 0.0;

    if (c0 < nchunks) stage_x(c0, 0);
    cpa_commit();

    int stg = 0;
    for (int c = c0; c < nchunks; c += gridDim.x, stg ^= 1) {
        const int nxt = c + gridDim.x;
        if (nxt < nchunks) stage_x(nxt, stg ^ 1);
        cpa_commit();
        asm volatile("cp.async.wait_group 1;");   // x(c) resident in sx[stg]
        __syncthreads();

        const long long row0 = (long long)c * BLK;
        long long rem = (long long)B - row0;
        const int rows = rem < BLK ? (int)rem : BLK;

        // Phase 1: per-row LSE from smem (72 B stride: conflict-free)
        if (tid < rows) {
            const float* rx = &sx[stg][tid * NC];
            float xr[NC];
            #pragma unroll
            for (int k = 0; k < NC; k++) xr[k] = rx[k];
            float m = xr[0];
            #pragma unroll
            for (int k = 1; k < NC; k++) m = fmaxf(m, xr[k]);
            float s = 0.f;
            #pragma unroll
            for (int k = 0; k < NC; k++) s += __expf(xr[k] - m);
            rowlse[tid] = m + __logf(s);
        }
        __syncthreads();

        // Phase 2: stream labels from gmem, elementwise l*(lse - x)
        {
            const int nf  = rows * NC;
            const int nv4 = nf >> 2;
            const float*  lb  = lab + row0 * NC;
            const float4* lb4 = (const float4*)lb;
            const float4* sxv = (const float4*)&sx[stg][0];

            for (int i = tid; i < nv4; i += BLK) {
                const float4 lv = lb4[i];      // LDG.128, fully coalesced
                const float4 xv = sxv[i];      // LDS.128, conflict-free
                const int e = i << 2;
                const float s0 = lv.x * (rowlse[(e    ) / NC] - xv.x);
                const float s1 = lv.y * (rowlse[(e + 1) / NC] - xv.y);
                const float s2 = lv.z * (rowlse[(e + 2) / NC] - xv.z);
                const float s3 = lv.w * (rowlse[(e + 3) / NC] - xv.w);
                acc += (double)((s0 + s1) + (s2 + s3));
            }
            for (int e = (nv4 << 2) + tid; e < nf; e += BLK)   // tail
                acc += (double)(lb[e] * (rowlse[e / NC] - sx[stg][e]));
        }
        __syncthreads();    // sx[stg] / rowlse reusable
    }
    asm volatile("cp.async.wait_group 0;");

    // ── per-block deterministic reduction ──
    #pragma unroll
    for (int o = 16; o > 0; o >>= 1)
        acc += __shfl_down_sync(0xffffffffu, acc, o);

    const int lane = tid & 31;
    const int warp = tid >> 5;
    if (lane == 0) sred[warp] = acc;
    __syncthreads();

    if (tid == 0) {
        g_partials[blockIdx.x] = sred[0] + sred[1] + sred[2] + sred[3];
        __threadfence();
        unsigned prev = atomicAdd(&g_count, 1u);
        s_last = (prev == gridDim.x - 1u) ? 1 : 0;
    }
    __syncthreads();

    // ── fused finalize: last block sums all partials ──
    if (s_last) {
        double v = 0.0;
        for (int i = tid; i < (int)gridDim.x; i += BLK)
            v += g_partials[i];
        #pragma unroll
        for (int o = 16; o > 0; o >>= 1)
            v += __shfl_down_sync(0xffffffffu, v, o);
        if (lane == 0) sred[warp] = v;
        __syncthreads();
        if (tid == 0) {
            out[0] = (float)((sred[0] + sred[1] + sred[2] + sred[3]) / (double)B);
            g_count = 0;    // reset for next graph replay
        }
    }
}

extern "C" void kernel_launch(void* const* d_in, const int* in_sizes, int n_in,
                              void* d_out, int out_size)
{
    const float* x   = (const float*)d_in[0];   // output       [B, 18]
    const float* lab = (const float*)d_in[1];   // labels_soft  [B, 18]
    const int B = in_sizes[0] / NC;
    const int nchunks = (B + BLK - 1) / BLK;

    int grid = 148 * 10;                // 10 blocks/SM (~19 KB smem each)
    if (grid > nchunks) grid = nchunks;
    if (grid > MAX_GRID) grid = MAX_GRID;

    ce_main_kernel<<<grid, BLK>>>(x, lab, (float*)d_out, B, nchunks);
}

// round 9
// speedup vs baseline: 1.6974x; 1.6974x over previous
#include <cuda_runtime.h>

// SoftmaxProbs: mean = (1/B) * sum_{b,c} l[b,c] * (lse_b - x[b,c])
// 2M rows x 18 classes fp32, HBM-bound (288 MB).
// x: cp.async double-buffered smem staging (row access for LSE, elementwise re-read).
// l: streamed from gmem with BATCHED LDG.128 (MLP=5 per thread) — never touches smem.

#define NC 18
#define BLK 256
#define CHUNK_F  (BLK * NC)          // 4608 floats per chunk
#define CHUNK_V4 (CHUNK_F / 4)       // 1152 float4
#define MAX_GRID 2048

__device__ double       g_partials[MAX_GRID];
__device__ unsigned int g_count = 0;

__device__ __forceinline__ void cpa16(unsigned int saddr, const float4* g) {
    asm volatile("cp.async.cg.shared.global [%0], [%1], 16;" :: "r"(saddr), "l"(g));
}
__device__ __forceinline__ void cpa_commit() {
    asm volatile("cp.async.commit_group;");
}

__global__ __launch_bounds__(BLK, 4)
void ce_main_kernel(const float* __restrict__ x,
                    const float* __restrict__ lab,
                    float* __restrict__ out,
                    int B, int nchunks)
{
    __shared__ float  sx[2][CHUNK_F];    // 36864 B
    __shared__ float  rowlse[BLK];       // 1024 B
    __shared__ double sred[BLK / 32];
    __shared__ int    s_last;

    const int tid = threadIdx.x;

    auto stage_x = [&](int c, int s) {
        const long long row0 = (long long)c * BLK;
        long long rem = (long long)B - row0;
        const int rows = rem < BLK ? (int)rem : BLK;
        const int nf   = rows * NC;
        const int nv4  = nf >> 2;
        const float*  xb  = x + row0 * NC;
        const float4* xb4 = (const float4*)xb;
        const unsigned int sxa = (unsigned int)__cvta_generic_to_shared(&sx[s][0]);
        for (int i = tid; i < nv4; i += BLK)
            cpa16(sxa + i * 16, xb4 + i);
        for (int i = (nv4 << 2) + tid; i < nf; i += BLK)   // tail (last chunk only)
            sx[s][i] = xb[i];
    };

    const int c0 = blockIdx.x;
    double acc = 0.0;

    if (c0 < nchunks) stage_x(c0, 0);
    cpa_commit();

    int stg = 0;
    for (int c = c0; c < nchunks; c += gridDim.x, stg ^= 1) {
        const int nxt = c + gridDim.x;
        if (nxt < nchunks) stage_x(nxt, stg ^ 1);
        cpa_commit();
        asm volatile("cp.async.wait_group 1;");   // x(c) resident in sx[stg]
        __syncthreads();

        const long long row0 = (long long)c * BLK;
        long long rem = (long long)B - row0;
        const int rows = rem < BLK ? (int)rem : BLK;

        // ── Phase 1: per-row LSE from smem (72 B stride: conflict-free) ──
        if (tid < rows) {
            const float* rx = &sx[stg][tid * NC];
            float xr[NC];
            #pragma unroll
            for (int k = 0; k < NC; k++) xr[k] = rx[k];
            float m = xr[0];
            #pragma unroll
            for (int k = 1; k < NC; k++) m = fmaxf(m, xr[k]);
            float s = 0.f;
            #pragma unroll
            for (int k = 0; k < NC; k++) s += __expf(xr[k] - m);
            rowlse[tid] = m + __logf(s);
        }
        __syncthreads();

        // ── Phase 2: labels from gmem, BATCHED loads, elementwise l*(lse-x) ──
        float facc = 0.f;
        const float*  lb  = lab + row0 * NC;
        const float4* lb4 = (const float4*)lb;
        const float4* sxv = (const float4*)&sx[stg][0];

        auto consume = [&](float4 lv, int i) {
            const float4 xv = sxv[i];          // LDS.128
            const int e = i << 2;
            facc += lv.x * (rowlse[(e    ) / NC] - xv.x);
            facc += lv.y * (rowlse[(e + 1) / NC] - xv.y);
            facc += lv.z * (rowlse[(e + 2) / NC] - xv.z);
            facc += lv.w * (rowlse[(e + 3) / NC] - xv.w);
        };

        if (rows == BLK) {
            // Full chunk: 1152 float4 over 256 threads = 4 each + 128 extra.
            // All loads issued back-to-back -> MLP 4-5 per thread.
            const float4 l0 = lb4[tid          ];
            const float4 l1 = lb4[tid +     BLK];
            const float4 l2 = lb4[tid + 2 * BLK];
            const float4 l3 = lb4[tid + 3 * BLK];
            float4 l4;
            const bool has5 = tid < (CHUNK_V4 - 4 * BLK);   // tid < 128
            if (has5) l4 = lb4[tid + 4 * BLK];

            consume(l0, tid          );
            consume(l1, tid +     BLK);
            consume(l2, tid + 2 * BLK);
            consume(l3, tid + 3 * BLK);
            if (has5) consume(l4, tid + 4 * BLK);
        } else {
            // Tail chunk (rare): generic path
            const int nf  = rows * NC;
            const int nv4 = nf >> 2;
            for (int i = tid; i < nv4; i += BLK)
                consume(lb4[i], i);
            for (int e = (nv4 << 2) + tid; e < nf; e += BLK)
                facc += lb[e] * (rowlse[e / NC] - sx[stg][e]);
        }
        acc += (double)facc;                    // one DADD per chunk
        __syncthreads();                        // sx[stg] / rowlse reusable
    }
    asm volatile("cp.async.wait_group 0;");

    // ── per-block deterministic reduction ──
    #pragma unroll
    for (int o = 16; o > 0; o >>= 1)
        acc += __shfl_down_sync(0xffffffffu, acc, o);

    const int lane = tid & 31;
    const int warp = tid >> 5;
    if (lane == 0) sred[warp] = acc;
    __syncthreads();

    if (tid == 0) {
        double v = 0.0;
        #pragma unroll
        for (int w = 0; w < BLK / 32; w++) v += sred[w];
        g_partials[blockIdx.x] = v;
        __threadfence();
        unsigned prev = atomicAdd(&g_count, 1u);
        s_last = (prev == gridDim.x - 1u) ? 1 : 0;
    }
    __syncthreads();

    // ── fused finalize: last block sums all partials ──
    if (s_last) {
        double v = 0.0;
        for (int i = tid; i < (int)gridDim.x; i += BLK)
            v += g_partials[i];
        #pragma unroll
        for (int o = 16; o > 0; o >>= 1)
            v += __shfl_down_sync(0xffffffffu, v, o);
        if (lane == 0) sred[warp] = v;
        __syncthreads();
        if (tid == 0) {
            double t = 0.0;
            #pragma unroll
            for (int w = 0; w < BLK / 32; w++) t += sred[w];
            out[0] = (float)(t / (double)B);
            g_count = 0;    // reset for next graph replay
        }
    }
}

extern "C" void kernel_launch(void* const* d_in, const int* in_sizes, int n_in,
                              void* d_out, int out_size)
{
    const float* x   = (const float*)d_in[0];   // output       [B, 18]
    const float* lab = (const float*)d_in[1];   // labels_soft  [B, 18]
    const int B = in_sizes[0] / NC;
    const int nchunks = (B + BLK - 1) / BLK;

    int grid = 148 * 4;                 // 4 blocks/SM (37 KB smem each)
    if (grid > nchunks) grid = nchunks;
    if (grid > MAX_GRID) grid = MAX_GRID;

    ce_main_kernel<<<grid, BLK>>>(x, lab, (float*)d_out, B, nchunks);
}